// round 15
// baseline (speedup 1.0000x reference)
#include <cuda_runtime.h>
#include <cuda_bf16.h>

typedef unsigned int u32;
typedef __nv_bfloat16 bf16;

// ---------------- problem constants ----------------
#define B_    64
#define T_    24
#define N_    300
#define F_    16
#define D_    64
#define C_    128
#define H_    12
#define BT_   (B_ * T_)        // 1536
#define BTN_  (BT_ * N_)       // 460800
#define ND_   (N_ * D_)        // 19200
#define MLPIN_ 19328
#define Q_    (BT_ * D_)       // 98304
#define NP    320              // padded node pitch (zero pad 300..319)
#define KSH_  (D_ * NP)        // 20480
#define KCONV (3 * KSH_)       // 61440

#define CSK    24
#define CKCH   2560
#define MLP1_SK   16
#define MLP1_KCH  1216

// hw2 smem
#define HW2_PB  328
#define HW2_PA  72
#define HW2_BOFF (2 * 64 * HW2_PA)
#define HW2_SMEM ((2 * 64 * HW2_PA + 2 * 64 * HW2_PB) * 2)

// chunk-32 pipeline: stage = A0|A1|B0|B1, each 128x40 bf16 (10240 B) -> 40960 B/stage
#define STGB   40960u
#define PIPE_DSM (2 * 40960)   // 81920 B dynamic smem, 2 CTAs/SM = 160 KB

// ---------------- scratch (device globals; zero-initialized) --------
__device__ bf16 g_Ah[(size_t)Q_ * NP];
__device__ bf16 g_Al[(size_t)Q_ * NP];
__device__ bf16 g_Bh[(size_t)Q_ * NP];
__device__ bf16 g_Bl[(size_t)Q_ * NP];
__device__ bf16 g_adjh[384 * NP];        // rows 300..383 stay zero
__device__ bf16 g_adjl[384 * NP];
__device__ bf16 g_w2th[64 * 64];
__device__ bf16 g_w2tl[64 * 64];
__device__ bf16 g_w1ph[(size_t)C_ * KCONV];
__device__ bf16 g_w1pl[(size_t)C_ * KCONV];
__device__ __align__(16) bf16 g_zero[32];
__device__ float g_y1part[(size_t)CSK * BT_ * C_];
__device__ float g_pooled[B_ * C_];
__device__ float g_z1part[MLP1_SK * B_ * 512];
__device__ float g_z2[B_ * 256];

__device__ __forceinline__ void split_bf16(float v, bf16& h, bf16& l) {
    h = __float2bfloat16(v);
    l = __float2bfloat16(v - __bfloat162float(h));
}
__device__ __forceinline__ void mma_bf16(float c[4], const u32 a[4], u32 b0, u32 b1) {
    asm volatile(
        "mma.sync.aligned.m16n8k16.row.col.f32.bf16.bf16.f32 "
        "{%0,%1,%2,%3},{%4,%5,%6,%7},{%8,%9},{%0,%1,%2,%3};\n"
        : "+f"(c[0]), "+f"(c[1]), "+f"(c[2]), "+f"(c[3])
        : "r"(a[0]), "r"(a[1]), "r"(a[2]), "r"(a[3]), "r"(b0), "r"(b1));
}
__device__ __forceinline__ u32 s2u(const void* p) { return (u32)__cvta_generic_to_shared(p); }
__device__ __forceinline__ void ldsm4(u32& r0, u32& r1, u32& r2, u32& r3, u32 a) {
    asm volatile("ldmatrix.sync.aligned.m8n8.x4.shared.b16 {%0,%1,%2,%3},[%4];\n"
                 : "=r"(r0), "=r"(r1), "=r"(r2), "=r"(r3) : "r"(a));
}
__device__ __forceinline__ void ldsm4t(u32& r0, u32& r1, u32& r2, u32& r3, u32 a) {
    asm volatile("ldmatrix.sync.aligned.m8n8.x4.trans.shared.b16 {%0,%1,%2,%3},[%4];\n"
                 : "=r"(r0), "=r"(r1), "=r"(r2), "=r"(r3) : "r"(a));
}
__device__ __forceinline__ void cp16(u32 d, const void* s) {
    asm volatile("cp.async.cg.shared.global [%0],[%1],16;\n" :: "r"(d), "l"(s));
}
#define CP_COMMIT() asm volatile("cp.async.commit_group;\n")
#define CP_WAIT0()  asm volatile("cp.async.wait_group 0;\n")

// ---------------- P0: split adj (pitch 320) and W2^T to bf16 hi/lo ----------------
__global__ void k_prep(const float* __restrict__ adj, const float* __restrict__ w2)
{
    int i = blockIdx.x * 256 + threadIdx.x;
    if (i < 300 * NP) {
        int m = i / NP, k = i - m * NP;
        float v = (k < 300) ? adj[m * 300 + k] : 0.f;
        split_bf16(v, g_adjh[i], g_adjl[i]);
    }
    int j = i - 300 * NP;
    if (j >= 0 && j < 4096) {
        int dp = j >> 6, d = j & 63;
        split_bf16(w2[d * 64 + dp], g_w2th[j], g_w2tl[j]);
    }
}

// ---------------- P1: repack conv_w1 ----------------
__global__ void k_repack(const float* __restrict__ w1)
{
    __shared__ float s[50 * 192];
    const int c  = blockIdx.x;
    const int nb = blockIdx.y;
    const int tid = threadIdx.x;
    const float* src = w1 + (size_t)c * 57600 + nb * 9600;
    for (int i = tid; i < 9600; i += 256) s[i] = src[i];
    __syncthreads();
    for (int j = tid; j < 9600; j += 256) {
        int nloc = j % 50;
        int t = j / 50;
        int d = t & 63, ksh = t >> 6;
        float v = s[nloc * 192 + d * 3 + ksh];
        size_t dst = (size_t)c * KCONV + ksh * KSH_ + d * NP + nb * 50 + nloc;
        split_bf16(v, g_w1ph[dst], g_w1pl[dst]);
    }
}

// ---------------- P2: S1 = x @ gcn_w1 -> (q, node) split ----------------
__global__ void k_xw1(const float* __restrict__ x, const float* __restrict__ w)
{
    __shared__ float ws[16 * 64];
    __shared__ float xs[64 * 16];
    __shared__ bf16 Th[64 * 66], Tl[64 * 66];
    __shared__ int btA[64], nA[64];
    const int tid  = threadIdx.x;
    const int row0 = blockIdx.x * 64;
    for (int i = tid; i < 1024; i += 256) ws[i] = w[i];
    for (int i = tid; i < 1024; i += 256) xs[i] = x[row0 * 16 + i];
    if (tid < 64) {
        int r = row0 + tid;
        btA[tid] = r / 300;
        nA[tid]  = r - btA[tid] * 300;
    }
    __syncthreads();
    for (int i = tid; i < 4096; i += 256) {
        int r = i >> 6, d = i & 63;
        float acc = 0.f;
        #pragma unroll
        for (int k = 0; k < 16; k++) acc = fmaf(xs[r * 16 + k], ws[k * 64 + d], acc);
        split_bf16(acc, Th[d * 66 + r], Tl[d * 66 + r]);
    }
    __syncthreads();
    for (int j = tid; j < 4096; j += 256) {
        int rr = j & 63, d = j >> 6;
        size_t addr = ((size_t)btA[rr] * 64 + d) * NP + nA[rr];
        g_Ah[addr] = Th[d * 66 + rr];
        g_Al[addr] = Tl[d * 66 + rr];
    }
}

// ---------------- K-A: adj GEMM, chunk-32 pipeline, templated tile width ------------
// O[q,m] = relu( sum_k S[q,k]*adj[m,k] + bias[q&63] ).
// NC=128: grid (768, 2) covers m 0..255.  NC=64: grid (768, 1) covers m 256..319.
// 256 thr, 2 CTAs/SM, 80KB dynamic smem, one sync per 32-k chunk.
template<int NC>
__global__ __launch_bounds__(256, 2) void k_adjmm(const bf16* __restrict__ Sh,
                                                  const bf16* __restrict__ Sl,
                                                  const float* __restrict__ bias,
                                                  bf16* __restrict__ Oh, bf16* __restrict__ Ol)
{
    extern __shared__ __align__(16) bf16 dsm[];
    const int q0 = blockIdx.x * 128;
    const int m0 = (NC == 128) ? blockIdx.y * 128 : 256;
    const int tid = threadIdx.x, warp = tid >> 5, lane = tid & 31;
    const int g = lane >> 2, tig = lane & 3;
    const int wm = warp >> 1, wn = warp & 1;
    const int grp = lane >> 3, lr = lane & 7;
    const u32 base = s2u(dsm);
    constexpr int NJ = NC / 16;       // 8 or 4
    constexpr int PL = NC / 32;       // 4 or 2
    u32 aOff[2];
    #pragma unroll
    for (int mi = 0; mi < 2; mi++) {
        int row = wm * 32 + mi * 16 + (grp & 1) * 8 + lr;
        aOff[mi] = (u32)(row * 40 + (grp >> 1) * 8) * 2;
    }
    const u32 bOff = 20480u + (u32)((wn * (NC / 2) + (grp >> 1) * 8 + lr) * 40 + (grp & 1) * 8) * 2;
    const int r_ = tid >> 2, sub_ = tid & 3;
    const bf16* aSrc = (sub_ < 2) ? Sh : Sl;
    const bf16* bSrc = (sub_ < 2) ? g_adjh : g_adjl;
    const int csel = (sub_ & 1) * 8;
    const u32 dcol = (u32)((sub_ >> 1) * 16 + csel) * 2;
    float c[2][NJ][4] = {};

    auto load32 = [&](int it, u32 st) {
        const int kk0 = it * 32;
        #pragma unroll
        for (int t2 = 0; t2 < 2; t2++) {
            const int kk = kk0 + t2 * 16;
            const u32 so = st + (u32)t2 * 10240u;
            #pragma unroll
            for (int t = 0; t < 2; t++) {
                int r = r_ + t * 64;
                u32 d = so + (u32)(r * 80) + dcol;
                cp16(base + d, aSrc + (size_t)(q0 + r) * NP + kk + csel);
                if (NC == 128 || t == 0)
                    cp16(base + 20480u + d, bSrc + (size_t)(m0 + r) * NP + kk + csel);
            }
        }
        CP_COMMIT();
    };

    load32(0, 0);
    for (int s = 0; s < 10; s++) {
        CP_WAIT0();
        __syncthreads();
        const u32 st = (u32)(s & 1) * STGB;
        #pragma unroll
        for (int t2 = 0; t2 < 2; t2++) {
            const u32 so = base + st + (u32)t2 * 10240u;
            u32 ah[2][4], al[2][4];
            #pragma unroll
            for (int mi = 0; mi < 2; mi++) {
                ldsm4(ah[mi][0], ah[mi][1], ah[mi][2], ah[mi][3], so + aOff[mi]);
                ldsm4(al[mi][0], al[mi][1], al[mi][2], al[mi][3], so + aOff[mi] + 32);
            }
            if (t2 == 0 && s < 9)
                load32(s + 1, (u32)((s & 1) ^ 1) * STGB);
            #pragma unroll
            for (int p = 0; p < PL; p++) {
                const u32 ba = so + bOff + p * 1280;
                u32 bh[4], bl[4];
                ldsm4(bh[0], bh[1], bh[2], bh[3], ba);
                ldsm4(bl[0], bl[1], bl[2], bl[3], ba + 32);
                #pragma unroll
                for (int mi = 0; mi < 2; mi++) {
                    mma_bf16(c[mi][2 * p],     ah[mi], bh[0], bh[1]);
                    mma_bf16(c[mi][2 * p],     ah[mi], bl[0], bl[1]);
                    mma_bf16(c[mi][2 * p],     al[mi], bh[0], bh[1]);
                    mma_bf16(c[mi][2 * p + 1], ah[mi], bh[2], bh[3]);
                    mma_bf16(c[mi][2 * p + 1], ah[mi], bl[2], bl[3]);
                    mma_bf16(c[mi][2 * p + 1], al[mi], bh[2], bh[3]);
                }
            }
        }
    }
    // epilogue: bias (by q), relu, split, store
    #pragma unroll
    for (int mi = 0; mi < 2; mi++) {
        int qlo = q0 + wm * 32 + mi * 16 + g;
        int qhi = qlo + 8;
        float b0 = bias[qlo & 63];
        float b1 = bias[qhi & 63];
        #pragma unroll
        for (int nj = 0; nj < NJ; nj++) {
            int m = m0 + wn * (NC / 2) + nj * 8 + tig * 2;
            if (m < 300) {
                float v00 = fmaxf(c[mi][nj][0] + b0, 0.f);
                float v01 = fmaxf(c[mi][nj][1] + b0, 0.f);
                float v10 = fmaxf(c[mi][nj][2] + b1, 0.f);
                float v11 = fmaxf(c[mi][nj][3] + b1, 0.f);
                bf16 h0, l0, h1, l1;
                __nv_bfloat162 ph, pl;
                split_bf16(v00, h0, l0); split_bf16(v01, h1, l1);
                ph.x = h0; ph.y = h1; pl.x = l0; pl.y = l1;
                *(__nv_bfloat162*)&Oh[(size_t)qlo * NP + m] = ph;
                *(__nv_bfloat162*)&Ol[(size_t)qlo * NP + m] = pl;
                split_bf16(v10, h0, l0); split_bf16(v11, h1, l1);
                ph.x = h0; ph.y = h1; pl.x = l0; pl.y = l1;
                *(__nv_bfloat162*)&Oh[(size_t)qhi * NP + m] = ph;
                *(__nv_bfloat162*)&Ol[(size_t)qhi * NP + m] = pl;
            }
        }
    }
}

// ---------------- K-B: hw2 gather-free per-bt GEMM (unchanged) ----------------------
__global__ __launch_bounds__(256) void k_hw2()
{
    extern __shared__ __align__(16) bf16 dyn2[];
    bf16* sAh = dyn2;
    bf16* sB  = dyn2 + HW2_BOFF;
    const int bt = blockIdx.x;
    const int tid = threadIdx.x, warp = tid >> 5, lane = tid & 31;
    const int g = lane >> 2, tig = lane & 3;
    const int wm_ = warp >> 1, wn_ = warp & 1;

    const bf16* hsrc = g_Bh + (size_t)bt * 64 * NP;
    const bf16* lsrc = g_Bl + (size_t)bt * 64 * NP;
    const u32 sBb = s2u(sB);
    for (int i = tid; i < 5120; i += 256) {
        int row = i / 40, c16 = i - (i / 40) * 40;
        const bf16* src = (row < 64) ? (hsrc + row * NP + c16 * 8)
                                     : (lsrc + (row - 64) * NP + c16 * 8);
        cp16(sBb + (u32)(row * HW2_PB * 2) + (u32)(c16 * 16), src);
    }
    const u32 sAb = s2u(sAh);
    for (int i = tid; i < 1024; i += 256) {
        int row = i >> 3, c16 = i & 7;
        const bf16* src = (row < 64) ? (g_w2th + row * 64 + c16 * 8)
                                     : (g_w2tl + (row - 64) * 64 + c16 * 8);
        cp16(sAb + (u32)(row * HW2_PA * 2) + (u32)(c16 * 16), src);
    }
    CP_COMMIT();
    CP_WAIT0();
    __syncthreads();

    const u32 aRow = (u32)(wm_ * 16 + ((lane >> 3) & 1) * 8 + (lane & 7));
    const u32 aCol = (u32)(((lane >> 3) >> 1) * 8);
    const u32 aAddrH = sAb + (aRow * HW2_PA + aCol) * 2;
    const u32 aAddrL = aAddrH + 64 * HW2_PA * 2;
    const u32 bKrow = (u32)(lane & 15);
    const u32 bNcol = (u32)(wn_ * 160 + (lane >> 4) * 8);
    const u32 bAddrH = sBb + (bKrow * HW2_PB + bNcol) * 2;
    const u32 bAddrL = bAddrH + 64 * HW2_PB * 2;

    float c[20][4] = {};
    #pragma unroll
    for (int kb = 0; kb < 64; kb += 16) {
        u32 ah[4], al[4];
        ldsm4(ah[0], ah[1], ah[2], ah[3], aAddrH + kb * 2);
        ldsm4(al[0], al[1], al[2], al[3], aAddrL + kb * 2);
        const u32 krowOff = (u32)(kb * HW2_PB * 2);
        #pragma unroll
        for (int nt = 0; nt < 10; nt++) {
            const u32 ncolOff = (u32)(nt * 16 * 2);
            u32 bh[4], bl[4];
            ldsm4t(bh[0], bh[1], bh[2], bh[3], bAddrH + krowOff + ncolOff);
            ldsm4t(bl[0], bl[1], bl[2], bl[3], bAddrL + krowOff + ncolOff);
            mma_bf16(c[2 * nt],     ah, bh[0], bh[1]);
            mma_bf16(c[2 * nt],     ah, bl[0], bl[1]);
            mma_bf16(c[2 * nt],     al, bh[0], bh[1]);
            mma_bf16(c[2 * nt + 1], ah, bh[2], bh[3]);
            mma_bf16(c[2 * nt + 1], ah, bl[2], bl[3]);
            mma_bf16(c[2 * nt + 1], al, bh[2], bh[3]);
        }
    }

    const int qlo = bt * 64 + wm_ * 16 + g;
    const int qhi = qlo + 8;
    #pragma unroll
    for (int j = 0; j < 20; j++) {
        int n = wn_ * 160 + (j >> 1) * 16 + (j & 1) * 8 + tig * 2;
        bf16 h0, l0, h1, l1;
        __nv_bfloat162 ph, pl;
        split_bf16(c[j][0], h0, l0); split_bf16(c[j][1], h1, l1);
        ph.x = h0; ph.y = h1; pl.x = l0; pl.y = l1;
        *(__nv_bfloat162*)&g_Ah[(size_t)qlo * NP + n] = ph;
        *(__nv_bfloat162*)&g_Al[(size_t)qlo * NP + n] = pl;
        split_bf16(c[j][2], h0, l0); split_bf16(c[j][3], h1, l1);
        ph.x = h0; ph.y = h1; pl.x = l0; pl.y = l1;
        *(__nv_bfloat162*)&g_Ah[(size_t)qhi * NP + n] = ph;
        *(__nv_bfloat162*)&g_Al[(size_t)qhi * NP + n] = pl;
    }
}

// ---------------- K-C: conv1 split-K GEMM, chunk-32 pipeline ------------------------
// grid (12 bt-tiles, 24 ks). M=bt(128), N=c(128), Kchunk=2560 in (ksh,d,n-320) order.
__global__ __launch_bounds__(256, 2) void k_conv1()
{
    extern __shared__ __align__(16) bf16 dsm[];
    __shared__ int rowBase[128];
    const int bt0 = blockIdx.x * 128;
    const int ks  = blockIdx.y;
    const int kb0 = ks * CKCH;
    const int ksh = kb0 / KSH_;
    const int koff = kb0 - ksh * KSH_;
    const int tid = threadIdx.x, warp = tid >> 5, lane = tid & 31;
    const int g = lane >> 2, tig = lane & 3;
    const int wm = warp >> 1, wn = warp & 1;
    const int grp = lane >> 3, lr = lane & 7;
    const u32 base = s2u(dsm);
    if (tid < 128) {
        int bt = bt0 + tid;
        int b = bt / T_, t = bt - b * T_;
        int tp = t + ksh - 1;
        rowBase[tid] = (tp >= 0 && tp < T_) ? ((b * T_ + tp) * KSH_) : -1;
    }
    __syncthreads();
    u32 aOff[2];
    #pragma unroll
    for (int mi = 0; mi < 2; mi++) {
        int row = wm * 32 + mi * 16 + (grp & 1) * 8 + lr;
        aOff[mi] = (u32)(row * 40 + (grp >> 1) * 8) * 2;
    }
    const u32 bOff = 20480u + (u32)((wn * 64 + (grp >> 1) * 8 + lr) * 40 + (grp & 1) * 8) * 2;
    const int r_ = tid >> 2, sub_ = tid & 3;
    const int base_ = rowBase[r_], base64_ = rowBase[r_ + 64];
    const bf16* aSrc = (sub_ < 2) ? g_Bh : g_Bl;
    const bf16* bSrc = (sub_ < 2) ? g_w1ph : g_w1pl;
    const int csel = (sub_ & 1) * 8;
    const u32 dcol = (u32)((sub_ >> 1) * 16 + csel) * 2;
    float c[2][8][4] = {};

    auto load32 = [&](int it, u32 st) {
        const int kk0 = it * 32;
        #pragma unroll
        for (int t2 = 0; t2 < 2; t2++) {
            const int kk = kk0 + t2 * 16;
            const u32 so = st + (u32)t2 * 10240u;
            #pragma unroll
            for (int t = 0; t < 2; t++) {
                int r = r_ + t * 64;
                u32 d = so + (u32)(r * 80) + dcol;
                int rb = t ? base64_ : base_;
                const bf16* sa = (rb >= 0) ? (aSrc + (size_t)rb + koff + kk + csel)
                                           : (g_zero + csel);
                cp16(base + d, sa);
                cp16(base + 20480u + d, bSrc + (size_t)r * KCONV + kb0 + kk + csel);
            }
        }
        CP_COMMIT();
    };

    load32(0, 0);
    for (int s = 0; s < CKCH / 32; s++) {
        CP_WAIT0();
        __syncthreads();
        const u32 st = (u32)(s & 1) * STGB;
        #pragma unroll
        for (int t2 = 0; t2 < 2; t2++) {
            const u32 so = base + st + (u32)t2 * 10240u;
            u32 ah[2][4], al[2][4];
            #pragma unroll
            for (int mi = 0; mi < 2; mi++) {
                ldsm4(ah[mi][0], ah[mi][1], ah[mi][2], ah[mi][3], so + aOff[mi]);
                ldsm4(al[mi][0], al[mi][1], al[mi][2], al[mi][3], so + aOff[mi] + 32);
            }
            if (t2 == 0 && s < CKCH / 32 - 1)
                load32(s + 1, (u32)((s & 1) ^ 1) * STGB);
            #pragma unroll
            for (int p = 0; p < 4; p++) {
                const u32 ba = so + bOff + p * 1280;
                u32 bh[4], bl[4];
                ldsm4(bh[0], bh[1], bh[2], bh[3], ba);
                ldsm4(bl[0], bl[1], bl[2], bl[3], ba + 32);
                #pragma unroll
                for (int mi = 0; mi < 2; mi++) {
                    mma_bf16(c[mi][2 * p],     ah[mi], bh[0], bh[1]);
                    mma_bf16(c[mi][2 * p],     ah[mi], bl[0], bl[1]);
                    mma_bf16(c[mi][2 * p],     al[mi], bh[0], bh[1]);
                    mma_bf16(c[mi][2 * p + 1], ah[mi], bh[2], bh[3]);
                    mma_bf16(c[mi][2 * p + 1], ah[mi], bl[2], bl[3]);
                    mma_bf16(c[mi][2 * p + 1], al[mi], bh[2], bh[3]);
                }
            }
        }
    }
    #pragma unroll
    for (int mi = 0; mi < 2; mi++) {
        int btlo = bt0 + wm * 32 + mi * 16 + g;
        int bthi = btlo + 8;
        #pragma unroll
        for (int nj = 0; nj < 8; nj++) {
            int cc = wn * 64 + nj * 8 + tig * 2;
            *(float2*)&g_y1part[((size_t)ks * BT_ + btlo) * C_ + cc] =
                make_float2(c[mi][nj][0], c[mi][nj][1]);
            *(float2*)&g_y1part[((size_t)ks * BT_ + bthi) * C_ + cc] =
                make_float2(c[mi][nj][2], c[mi][nj][3]);
        }
    }
}

// ---------------- K-D: conv2 + relu + temporal mean-pool ----------------
__global__ void k_conv2pool(const float* __restrict__ cb1,
                            const float* __restrict__ w2,
                            const float* __restrict__ cb2)
{
    __shared__ float ys[C_ * 26];
    const int b = blockIdx.x;
    const int tid = threadIdx.x;
    for (int i = tid; i < C_ * T_; i += 256) {
        int c = i & 127, t = i >> 7;
        float v = cb1[c];
        #pragma unroll
        for (int s = 0; s < CSK; s++)
            v += g_y1part[((size_t)s * BT_ + b * T_ + t) * C_ + c];
        ys[c * 26 + t + 1] = fmaxf(v, 0.f);
    }
    if (tid < C_) { ys[tid * 26 + 0] = 0.f; ys[tid * 26 + 25] = 0.f; }
    __syncthreads();

    const int c = tid >> 1;
    const int half = tid & 1;
    const int tbase = half * 12;
    const float bias2 = cb2[c];
    const float* wrow = w2 + c * (C_ * 3);
    float acc[12];
    #pragma unroll
    for (int tt = 0; tt < 12; tt++) acc[tt] = bias2;
    for (int c1 = 0; c1 < C_; c1++) {
        float w0 = wrow[c1 * 3 + 0];
        float w1 = wrow[c1 * 3 + 1];
        float w2v = wrow[c1 * 3 + 2];
        float yv[14];
        #pragma unroll
        for (int idx = 0; idx < 14; idx++) yv[idx] = ys[c1 * 26 + tbase + idx];
        #pragma unroll
        for (int tt = 0; tt < 12; tt++)
            acc[tt] += w0 * yv[tt] + w1 * yv[tt + 1] + w2v * yv[tt + 2];
    }
    float s = 0.f;
    #pragma unroll
    for (int tt = 0; tt < 12; tt++) s += fmaxf(acc[tt], 0.f);
    s += __shfl_xor_sync(0xffffffffu, s, 1);
    if (half == 0) g_pooled[b * C_ + c] = s * (1.f / 24.f);
}

// ---------------- K-E: MLP1 split-K 16, fp32 scalar ----------------
__global__ void k_mlp1(const float* __restrict__ w)
{
    const int n0  = blockIdx.x * 64;
    const int kc0 = blockIdx.y * MLP1_KCH;
    __shared__ float Ast[16][68];
    __shared__ float Bs[16][68];
    const int tid = threadIdx.x;
    const int tx = tid & 15, ty = tid >> 4;
    float acc[4][4] = {};
    for (int k0 = 0; k0 < MLP1_KCH; k0 += 16) {
        for (int i = tid; i < 1024; i += 256) {
            int r = i >> 4, k = i & 15;
            int kg = kc0 + k0 + k;
            float v;
            if (kg < ND_) {
                int nn = kg >> 6, d = kg & 63;
                size_t a = ((size_t)((r * T_ + (T_ - 1)) * 64 + d)) * NP + nn;
                v = __bfloat162float(g_Bh[a]) + __bfloat162float(g_Bl[a]);
            } else if (kg < MLPIN_) {
                v = g_pooled[r * C_ + (kg - ND_)];
            } else {
                v = 0.f;
            }
            Ast[k][r] = v;
        }
        for (int i = tid; i < 1024; i += 256) {
            int k = i >> 6, d = i & 63;
            int kg = kc0 + k0 + k;
            Bs[k][d] = (kg < MLPIN_) ? w[(size_t)kg * 512 + n0 + d] : 0.f;
        }
        __syncthreads();
        #pragma unroll
        for (int k = 0; k < 16; k++) {
            float4 a4 = *reinterpret_cast<const float4*>(&Ast[k][ty * 4]);
            float4 b4 = *reinterpret_cast<const float4*>(&Bs[k][tx * 4]);
            float a[4] = {a4.x, a4.y, a4.z, a4.w};
            float b[4] = {b4.x, b4.y, b4.z, b4.w};
            #pragma unroll
            for (int i = 0; i < 4; i++)
                #pragma unroll
                for (int j = 0; j < 4; j++) acc[i][j] = fmaf(a[i], b[j], acc[i][j]);
        }
        __syncthreads();
    }
    const int ks = blockIdx.y;
    #pragma unroll
    for (int i = 0; i < 4; i++)
        #pragma unroll
        for (int j = 0; j < 4; j++)
            g_z1part[(ks * B_ + ty * 4 + i) * 512 + n0 + tx * 4 + j] = acc[i][j];
}

// ---------------- K-F: MLP2 ----------------
__global__ void k_mlp2(const float* __restrict__ mb1, const float* __restrict__ w,
                       const float* __restrict__ mb2)
{
    const int n0 = blockIdx.x * 64;
    __shared__ float Ast[16][68];
    __shared__ float Bs[16][68];
    const int tid = threadIdx.x;
    const int tx = tid & 15, ty = tid >> 4;
    float acc[4][4] = {};
    for (int k0 = 0; k0 < 512; k0 += 16) {
        for (int i = tid; i < 1024; i += 256) {
            int r = i >> 4, k = i & 15;
            int kg = k0 + k;
            float v = mb1[kg];
            #pragma unroll
            for (int s = 0; s < MLP1_SK; s++) v += g_z1part[(s * B_ + r) * 512 + kg];
            Ast[k][r] = fmaxf(v, 0.f);
        }
        for (int i = tid; i < 1024; i += 256) {
            int k = i >> 6, d = i & 63;
            Bs[k][d] = w[(k0 + k) * 256 + n0 + d];
        }
        __syncthreads();
        #pragma unroll
        for (int k = 0; k < 16; k++) {
            float4 a4 = *reinterpret_cast<const float4*>(&Ast[k][ty * 4]);
            float4 b4 = *reinterpret_cast<const float4*>(&Bs[k][tx * 4]);
            float a[4] = {a4.x, a4.y, a4.z, a4.w};
            float b[4] = {b4.x, b4.y, b4.z, b4.w};
            #pragma unroll
            for (int i = 0; i < 4; i++)
                #pragma unroll
                for (int j = 0; j < 4; j++) acc[i][j] = fmaf(a[i], b[j], acc[i][j]);
        }
        __syncthreads();
    }
    #pragma unroll
    for (int i = 0; i < 4; i++)
        #pragma unroll
        for (int j = 0; j < 4; j++) {
            int n = n0 + tx * 4 + j;
            g_z2[(ty * 4 + i) * 256 + n] = fmaxf(acc[i][j] + mb2[n], 0.f);
        }
}

// ---------------- K-G: MLP3 -> d_out ----------------
__global__ void k_mlp3(const float* __restrict__ w, const float* __restrict__ mb3,
                       float* __restrict__ out)
{
    const int n0 = blockIdx.x * 64;
    __shared__ float Ast[16][68];
    __shared__ float Bs[16][68];
    const int tid = threadIdx.x;
    const int tx = tid & 15, ty = tid >> 4;
    float acc[4][4] = {};
    for (int k0 = 0; k0 < 256; k0 += 16) {
        for (int i = tid; i < 1024; i += 256) {
            int r = i >> 4, k = i & 15;
            Ast[k][r] = g_z2[r * 256 + k0 + k];
        }
        for (int i = tid; i < 1024; i += 256) {
            int k = i >> 6, d = i & 63;
            int n = n0 + d;
            Bs[k][d] = (n < N_ * H_) ? w[(k0 + k) * (N_ * H_) + n] : 0.f;
        }
        __syncthreads();
        #pragma unroll
        for (int k = 0; k < 16; k++) {
            float4 a4 = *reinterpret_cast<const float4*>(&Ast[k][ty * 4]);
            float4 b4 = *reinterpret_cast<const float4*>(&Bs[k][tx * 4]);
            float a[4] = {a4.x, a4.y, a4.z, a4.w};
            float b[4] = {b4.x, b4.y, b4.z, b4.w};
            #pragma unroll
            for (int i = 0; i < 4; i++)
                #pragma unroll
                for (int j = 0; j < 4; j++) acc[i][j] = fmaf(a[i], b[j], acc[i][j]);
        }
        __syncthreads();
    }
    #pragma unroll
    for (int i = 0; i < 4; i++)
        #pragma unroll
        for (int j = 0; j < 4; j++) {
            int n = n0 + tx * 4 + j;
            if (n < N_ * H_)
                out[(ty * 4 + i) * (N_ * H_) + n] = acc[i][j] + mb3[n];
        }
}

// ---------------- launch ----------------
extern "C" void kernel_launch(void* const* d_in, const int* in_sizes, int n_in,
                              void* d_out, int out_size)
{
    const float* x    = (const float*)d_in[0];
    const float* adj  = (const float*)d_in[1];
    const float* gw1  = (const float*)d_in[2];
    const float* gb1  = (const float*)d_in[3];
    const float* gw2  = (const float*)d_in[4];
    const float* gb2  = (const float*)d_in[5];
    const float* cw1  = (const float*)d_in[6];
    const float* cb1  = (const float*)d_in[7];
    const float* cw2  = (const float*)d_in[8];
    const float* cb2  = (const float*)d_in[9];
    const float* mw1  = (const float*)d_in[10];
    const float* mb1  = (const float*)d_in[11];
    const float* mw2  = (const float*)d_in[12];
    const float* mb2  = (const float*)d_in[13];
    const float* mw3  = (const float*)d_in[14];
    const float* mb3  = (const float*)d_in[15];
    float* out = (float*)d_out;

    bf16 *Ah, *Al, *Bh, *Bl;
    cudaGetSymbolAddress((void**)&Ah, g_Ah);
    cudaGetSymbolAddress((void**)&Al, g_Al);
    cudaGetSymbolAddress((void**)&Bh, g_Bh);
    cudaGetSymbolAddress((void**)&Bl, g_Bl);

    cudaFuncSetAttribute(k_hw2, cudaFuncAttributeMaxDynamicSharedMemorySize, HW2_SMEM);
    cudaFuncSetAttribute(k_adjmm<128>, cudaFuncAttributeMaxDynamicSharedMemorySize, PIPE_DSM);
    cudaFuncSetAttribute(k_adjmm<64>,  cudaFuncAttributeMaxDynamicSharedMemorySize, PIPE_DSM);
    cudaFuncSetAttribute(k_conv1, cudaFuncAttributeMaxDynamicSharedMemorySize, PIPE_DSM);

    k_prep<<<(300 * NP + 4096 + 255) / 256, 256>>>(adj, gw2);
    k_repack<<<dim3(C_, 6), 256>>>(cw1);
    k_xw1<<<BTN_ / 64, 256>>>(x, gw1);                                    // S1 -> A
    k_adjmm<128><<<dim3(Q_ / 128, 2), 256, PIPE_DSM>>>(Ah, Al, gb1, Bh, Bl);
    k_adjmm<64><<<dim3(Q_ / 128, 1), 256, PIPE_DSM>>>(Ah, Al, gb1, Bh, Bl); // h1 -> B
    k_hw2<<<BT_, 256, HW2_SMEM>>>();                                      // S2 -> A
    k_adjmm<128><<<dim3(Q_ / 128, 2), 256, PIPE_DSM>>>(Ah, Al, gb2, Bh, Bl);
    k_adjmm<64><<<dim3(Q_ / 128, 1), 256, PIPE_DSM>>>(Ah, Al, gb2, Bh, Bl); // h2 -> B
    k_conv1<<<dim3(BT_ / 128, CSK), 256, PIPE_DSM>>>();
    k_conv2pool<<<B_, 256>>>(cb1, cw2, cb2);
    k_mlp1<<<dim3(512 / 64, MLP1_SK), 256>>>(mw1);
    k_mlp2<<<256 / 64, 256>>>(mb1, mw2, mb2);
    k_mlp3<<<(N_ * H_ + 63) / 64, 256>>>(mw3, mb3, out);
}

// round 16
// speedup vs baseline: 1.0240x; 1.0240x over previous
#include <cuda_runtime.h>
#include <cuda_bf16.h>

typedef unsigned int u32;
typedef __nv_bfloat16 bf16;

// ---------------- problem constants ----------------
#define B_    64
#define T_    24
#define N_    300
#define F_    16
#define D_    64
#define C_    128
#define H_    12
#define BT_   (B_ * T_)        // 1536
#define BTN_  (BT_ * N_)       // 460800
#define ND_   (N_ * D_)        // 19200
#define MLPIN_ 19328
#define Q_    (BT_ * D_)       // 98304
#define NP    320              // padded node pitch (zero pad 300..319)
#define KSH_  (D_ * NP)        // 20480
#define KCONV (3 * KSH_)       // 61440

#define CSK    24
#define CKCH   2560
#define MLP1_SK   16
#define MLP1_KCH  1216

// hw2 smem
#define HW2_PB  328
#define HW2_PA  72
#define HW2_BOFF (2 * 64 * HW2_PA)
#define HW2_SMEM ((2 * 64 * HW2_PA + 2 * 64 * HW2_PB) * 2)

// ---------------- scratch (device globals; zero-initialized) --------
__device__ bf16 g_Ah[(size_t)Q_ * NP];
__device__ bf16 g_Al[(size_t)Q_ * NP];
__device__ bf16 g_Bh[(size_t)Q_ * NP];
__device__ bf16 g_Bl[(size_t)Q_ * NP];
__device__ bf16 g_adjh[384 * NP];        // rows 300..383 stay zero
__device__ bf16 g_adjl[384 * NP];
__device__ bf16 g_w2th[64 * 64];
__device__ bf16 g_w2tl[64 * 64];
__device__ bf16 g_w1ph[(size_t)C_ * KCONV];
__device__ bf16 g_w1pl[(size_t)C_ * KCONV];
__device__ __align__(16) bf16 g_zero[32];
__device__ float g_y1part[(size_t)CSK * BT_ * C_];
__device__ float g_pooled[B_ * C_];
__device__ float g_z1part[MLP1_SK * B_ * 512];
__device__ float g_z2[B_ * 256];

__device__ __forceinline__ void split_bf16(float v, bf16& h, bf16& l) {
    h = __float2bfloat16(v);
    l = __float2bfloat16(v - __bfloat162float(h));
}
__device__ __forceinline__ void mma_bf16(float c[4], const u32 a[4], u32 b0, u32 b1) {
    asm volatile(
        "mma.sync.aligned.m16n8k16.row.col.f32.bf16.bf16.f32 "
        "{%0,%1,%2,%3},{%4,%5,%6,%7},{%8,%9},{%0,%1,%2,%3};\n"
        : "+f"(c[0]), "+f"(c[1]), "+f"(c[2]), "+f"(c[3])
        : "r"(a[0]), "r"(a[1]), "r"(a[2]), "r"(a[3]), "r"(b0), "r"(b1));
}
__device__ __forceinline__ u32 s2u(const void* p) { return (u32)__cvta_generic_to_shared(p); }
__device__ __forceinline__ void ldsm4(u32& r0, u32& r1, u32& r2, u32& r3, u32 a) {
    asm volatile("ldmatrix.sync.aligned.m8n8.x4.shared.b16 {%0,%1,%2,%3},[%4];\n"
                 : "=r"(r0), "=r"(r1), "=r"(r2), "=r"(r3) : "r"(a));
}
__device__ __forceinline__ void ldsm4t(u32& r0, u32& r1, u32& r2, u32& r3, u32 a) {
    asm volatile("ldmatrix.sync.aligned.m8n8.x4.trans.shared.b16 {%0,%1,%2,%3},[%4];\n"
                 : "=r"(r0), "=r"(r1), "=r"(r2), "=r"(r3) : "r"(a));
}
__device__ __forceinline__ void cp16(u32 d, const void* s) {
    asm volatile("cp.async.cg.shared.global [%0],[%1],16;\n" :: "r"(d), "l"(s));
}
#define CP_COMMIT() asm volatile("cp.async.commit_group;\n")
#define CP_WAIT0()  asm volatile("cp.async.wait_group 0;\n")

// ---------------- P0: split adj (pitch 320) and W2^T to bf16 hi/lo ----------------
__global__ void k_prep(const float* __restrict__ adj, const float* __restrict__ w2)
{
    int i = blockIdx.x * 256 + threadIdx.x;
    if (i < 300 * NP) {
        int m = i / NP, k = i - m * NP;
        float v = (k < 300) ? adj[m * 300 + k] : 0.f;
        split_bf16(v, g_adjh[i], g_adjl[i]);
    }
    int j = i - 300 * NP;
    if (j >= 0 && j < 4096) {
        int dp = j >> 6, d = j & 63;
        split_bf16(w2[d * 64 + dp], g_w2th[j], g_w2tl[j]);
    }
}

// ---------------- P1: repack conv_w1 ----------------
__global__ void k_repack(const float* __restrict__ w1)
{
    __shared__ float s[50 * 192];
    const int c  = blockIdx.x;
    const int nb = blockIdx.y;
    const int tid = threadIdx.x;
    const float* src = w1 + (size_t)c * 57600 + nb * 9600;
    for (int i = tid; i < 9600; i += 256) s[i] = src[i];
    __syncthreads();
    for (int j = tid; j < 9600; j += 256) {
        int nloc = j % 50;
        int t = j / 50;
        int d = t & 63, ksh = t >> 6;
        float v = s[nloc * 192 + d * 3 + ksh];
        size_t dst = (size_t)c * KCONV + ksh * KSH_ + d * NP + nb * 50 + nloc;
        split_bf16(v, g_w1ph[dst], g_w1pl[dst]);
    }
}

// ---------------- P2: S1 = x @ gcn_w1 -> (q, node) split ----------------
__global__ void k_xw1(const float* __restrict__ x, const float* __restrict__ w)
{
    __shared__ float ws[16 * 64];
    __shared__ float xs[64 * 16];
    __shared__ bf16 Th[64 * 66], Tl[64 * 66];
    __shared__ int btA[64], nA[64];
    const int tid  = threadIdx.x;
    const int row0 = blockIdx.x * 64;
    for (int i = tid; i < 1024; i += 256) ws[i] = w[i];
    for (int i = tid; i < 1024; i += 256) xs[i] = x[row0 * 16 + i];
    if (tid < 64) {
        int r = row0 + tid;
        btA[tid] = r / 300;
        nA[tid]  = r - btA[tid] * 300;
    }
    __syncthreads();
    for (int i = tid; i < 4096; i += 256) {
        int r = i >> 6, d = i & 63;
        float acc = 0.f;
        #pragma unroll
        for (int k = 0; k < 16; k++) acc = fmaf(xs[r * 16 + k], ws[k * 64 + d], acc);
        split_bf16(acc, Th[d * 66 + r], Tl[d * 66 + r]);
    }
    __syncthreads();
    for (int j = tid; j < 4096; j += 256) {
        int rr = j & 63, d = j >> 6;
        size_t addr = ((size_t)btA[rr] * 64 + d) * NP + nA[rr];
        g_Ah[addr] = Th[d * 66 + rr];
        g_Al[addr] = Tl[d * 66 + rr];
    }
}

// ---------------- K-A: adj GEMM, chunk-16 pipeline (R11 winner), templated NC -------
// O[q,m] = relu( sum_k S[q,k]*adj[m,k] + bias[q&63] ).
// NC=128: grid (768, 2) -> m 0..255.  NC=64: grid (768, 1) -> m 256..319.
// 256 thr, 2 CTAs/SM, single __syncthreads per chunk, prefetch after ldsm-A.
template<int NC>
__global__ __launch_bounds__(256, 2) void k_adjmm(const bf16* __restrict__ Sh,
                                                  const bf16* __restrict__ Sl,
                                                  const float* __restrict__ bias,
                                                  bf16* __restrict__ Oh, bf16* __restrict__ Ol)
{
    __shared__ __align__(16) bf16 sA[2][128 * 40];
    __shared__ __align__(16) bf16 sB[2][128 * 40];
    const int q0 = blockIdx.x * 128;
    const int m0 = (NC == 128) ? blockIdx.y * 128 : 256;
    const int tid = threadIdx.x, warp = tid >> 5, lane = tid & 31;
    const int g = lane >> 2, tig = lane & 3;
    const int wm = warp >> 1, wn = warp & 1;
    const int grp = lane >> 3, lr = lane & 7;
    const u32 saB = s2u(&sA[0][0]), sbB = s2u(&sB[0][0]);
    const u32 BUF = 128 * 40 * 2;
    constexpr int NJ = NC / 16;       // 8 or 4
    constexpr int PL = NC / 32;       // 4 or 2
    u32 aAddr[2];
    #pragma unroll
    for (int mi = 0; mi < 2; mi++) {
        int row = wm * 32 + mi * 16 + (grp & 1) * 8 + lr;
        aAddr[mi] = saB + (row * 40 + (grp >> 1) * 8) * 2;
    }
    const u32 bAddr = sbB + ((wn * (NC / 2) + (grp >> 1) * 8 + lr) * 40 + (grp & 1) * 8) * 2;
    const int r_ = tid >> 2, sub_ = tid & 3;
    const bf16* aSrc = (sub_ < 2) ? Sh : Sl;
    const bf16* bSrc = (sub_ < 2) ? g_adjh : g_adjl;
    const int csel = (sub_ & 1) * 8;
    const u32 dcol = (u32)((sub_ >> 1) * 16 + csel) * 2;
    float c[2][NJ][4] = {};

    // prologue: chunk 0 into buf 0
    #pragma unroll
    for (int t = 0; t < 2; t++) {
        int r = r_ + t * 64;
        u32 d = (u32)(r * 80) + dcol;
        cp16(saB + d, aSrc + (size_t)(q0 + r) * NP + csel);
        if (NC == 128 || t == 0)
            cp16(sbB + d, bSrc + (size_t)(m0 + r) * NP + csel);
    }
    CP_COMMIT();

    for (int s = 0; s < 20; s++) {
        const int bi = s & 1;
        CP_WAIT0();
        __syncthreads();
        const u32 bo = bi * BUF;
        u32 ah[2][4], al[2][4];
        #pragma unroll
        for (int mi = 0; mi < 2; mi++) {
            ldsm4(ah[mi][0], ah[mi][1], ah[mi][2], ah[mi][3], aAddr[mi] + bo);
            ldsm4(al[mi][0], al[mi][1], al[mi][2], al[mi][3], aAddr[mi] + bo + 32);
        }
        if (s < 19) {
            const int kk0 = (s + 1) * 16;
            const u32 bo2 = (bi ^ 1) * BUF;
            #pragma unroll
            for (int t = 0; t < 2; t++) {
                int r = r_ + t * 64;
                u32 d = bo2 + (u32)(r * 80) + dcol;
                cp16(saB + d, aSrc + (size_t)(q0 + r) * NP + kk0 + csel);
                if (NC == 128 || t == 0)
                    cp16(sbB + d, bSrc + (size_t)(m0 + r) * NP + kk0 + csel);
            }
            CP_COMMIT();
        }
        #pragma unroll
        for (int p = 0; p < PL; p++) {
            const u32 ba = bAddr + bo + p * 1280;    // p*16 rows * 80B
            u32 bh[4], bl[4];
            ldsm4(bh[0], bh[1], bh[2], bh[3], ba);
            ldsm4(bl[0], bl[1], bl[2], bl[3], ba + 32);
            #pragma unroll
            for (int mi = 0; mi < 2; mi++) {
                mma_bf16(c[mi][2 * p],     ah[mi], bh[0], bh[1]);
                mma_bf16(c[mi][2 * p],     ah[mi], bl[0], bl[1]);
                mma_bf16(c[mi][2 * p],     al[mi], bh[0], bh[1]);
                mma_bf16(c[mi][2 * p + 1], ah[mi], bh[2], bh[3]);
                mma_bf16(c[mi][2 * p + 1], ah[mi], bl[2], bl[3]);
                mma_bf16(c[mi][2 * p + 1], al[mi], bh[2], bh[3]);
            }
        }
    }
    // epilogue: bias (by q), relu, split, store
    #pragma unroll
    for (int mi = 0; mi < 2; mi++) {
        int qlo = q0 + wm * 32 + mi * 16 + g;
        int qhi = qlo + 8;
        float b0 = bias[qlo & 63];
        float b1 = bias[qhi & 63];
        #pragma unroll
        for (int nj = 0; nj < NJ; nj++) {
            int m = m0 + wn * (NC / 2) + nj * 8 + tig * 2;
            if (m < 300) {
                float v00 = fmaxf(c[mi][nj][0] + b0, 0.f);
                float v01 = fmaxf(c[mi][nj][1] + b0, 0.f);
                float v10 = fmaxf(c[mi][nj][2] + b1, 0.f);
                float v11 = fmaxf(c[mi][nj][3] + b1, 0.f);
                bf16 h0, l0, h1, l1;
                __nv_bfloat162 ph, pl;
                split_bf16(v00, h0, l0); split_bf16(v01, h1, l1);
                ph.x = h0; ph.y = h1; pl.x = l0; pl.y = l1;
                *(__nv_bfloat162*)&Oh[(size_t)qlo * NP + m] = ph;
                *(__nv_bfloat162*)&Ol[(size_t)qlo * NP + m] = pl;
                split_bf16(v10, h0, l0); split_bf16(v11, h1, l1);
                ph.x = h0; ph.y = h1; pl.x = l0; pl.y = l1;
                *(__nv_bfloat162*)&Oh[(size_t)qhi * NP + m] = ph;
                *(__nv_bfloat162*)&Ol[(size_t)qhi * NP + m] = pl;
            }
        }
    }
}

// ---------------- K-B: hw2 gather-free per-bt GEMM (unchanged from R11) -------------
__global__ __launch_bounds__(256) void k_hw2()
{
    extern __shared__ __align__(16) bf16 dyn2[];
    bf16* sAh = dyn2;
    bf16* sB  = dyn2 + HW2_BOFF;
    const int bt = blockIdx.x;
    const int tid = threadIdx.x, warp = tid >> 5, lane = tid & 31;
    const int g = lane >> 2, tig = lane & 3;
    const int wm_ = warp >> 1, wn_ = warp & 1;

    const bf16* hsrc = g_Bh + (size_t)bt * 64 * NP;
    const bf16* lsrc = g_Bl + (size_t)bt * 64 * NP;
    const u32 sBb = s2u(sB);
    for (int i = tid; i < 5120; i += 256) {
        int row = i / 40, c16 = i - (i / 40) * 40;
        const bf16* src = (row < 64) ? (hsrc + row * NP + c16 * 8)
                                     : (lsrc + (row - 64) * NP + c16 * 8);
        cp16(sBb + (u32)(row * HW2_PB * 2) + (u32)(c16 * 16), src);
    }
    const u32 sAb = s2u(sAh);
    for (int i = tid; i < 1024; i += 256) {
        int row = i >> 3, c16 = i & 7;
        const bf16* src = (row < 64) ? (g_w2th + row * 64 + c16 * 8)
                                     : (g_w2tl + (row - 64) * 64 + c16 * 8);
        cp16(sAb + (u32)(row * HW2_PA * 2) + (u32)(c16 * 16), src);
    }
    CP_COMMIT();
    CP_WAIT0();
    __syncthreads();

    const u32 aRow = (u32)(wm_ * 16 + ((lane >> 3) & 1) * 8 + (lane & 7));
    const u32 aCol = (u32)(((lane >> 3) >> 1) * 8);
    const u32 aAddrH = sAb + (aRow * HW2_PA + aCol) * 2;
    const u32 aAddrL = aAddrH + 64 * HW2_PA * 2;
    const u32 bKrow = (u32)(lane & 15);
    const u32 bNcol = (u32)(wn_ * 160 + (lane >> 4) * 8);
    const u32 bAddrH = sBb + (bKrow * HW2_PB + bNcol) * 2;
    const u32 bAddrL = bAddrH + 64 * HW2_PB * 2;

    float c[20][4] = {};
    #pragma unroll
    for (int kb = 0; kb < 64; kb += 16) {
        u32 ah[4], al[4];
        ldsm4(ah[0], ah[1], ah[2], ah[3], aAddrH + kb * 2);
        ldsm4(al[0], al[1], al[2], al[3], aAddrL + kb * 2);
        const u32 krowOff = (u32)(kb * HW2_PB * 2);
        #pragma unroll
        for (int nt = 0; nt < 10; nt++) {
            const u32 ncolOff = (u32)(nt * 16 * 2);
            u32 bh[4], bl[4];
            ldsm4t(bh[0], bh[1], bh[2], bh[3], bAddrH + krowOff + ncolOff);
            ldsm4t(bl[0], bl[1], bl[2], bl[3], bAddrL + krowOff + ncolOff);
            mma_bf16(c[2 * nt],     ah, bh[0], bh[1]);
            mma_bf16(c[2 * nt],     ah, bl[0], bl[1]);
            mma_bf16(c[2 * nt],     al, bh[0], bh[1]);
            mma_bf16(c[2 * nt + 1], ah, bh[2], bh[3]);
            mma_bf16(c[2 * nt + 1], ah, bl[2], bl[3]);
            mma_bf16(c[2 * nt + 1], al, bh[2], bh[3]);
        }
    }

    const int qlo = bt * 64 + wm_ * 16 + g;
    const int qhi = qlo + 8;
    #pragma unroll
    for (int j = 0; j < 20; j++) {
        int n = wn_ * 160 + (j >> 1) * 16 + (j & 1) * 8 + tig * 2;
        bf16 h0, l0, h1, l1;
        __nv_bfloat162 ph, pl;
        split_bf16(c[j][0], h0, l0); split_bf16(c[j][1], h1, l1);
        ph.x = h0; ph.y = h1; pl.x = l0; pl.y = l1;
        *(__nv_bfloat162*)&g_Ah[(size_t)qlo * NP + n] = ph;
        *(__nv_bfloat162*)&g_Al[(size_t)qlo * NP + n] = pl;
        split_bf16(c[j][2], h0, l0); split_bf16(c[j][3], h1, l1);
        ph.x = h0; ph.y = h1; pl.x = l0; pl.y = l1;
        *(__nv_bfloat162*)&g_Ah[(size_t)qhi * NP + n] = ph;
        *(__nv_bfloat162*)&g_Al[(size_t)qhi * NP + n] = pl;
    }
}

// ---------------- K-C: conv1 split-K GEMM (R11 chunk-16 winner, unchanged) ----------
__global__ __launch_bounds__(256, 2) void k_conv1()
{
    __shared__ __align__(16) bf16 sA[2][128 * 40];
    __shared__ __align__(16) bf16 sB[2][128 * 40];
    __shared__ int rowBase[128];
    const int bt0 = blockIdx.x * 128;
    const int ks  = blockIdx.y;
    const int kb0 = ks * CKCH;
    const int ksh = kb0 / KSH_;
    const int koff = kb0 - ksh * KSH_;
    const int tid = threadIdx.x, warp = tid >> 5, lane = tid & 31;
    const int g = lane >> 2, tig = lane & 3;
    const int wm = warp >> 1, wn = warp & 1;
    const int grp = lane >> 3, lr = lane & 7;
    const u32 saB = s2u(&sA[0][0]), sbB = s2u(&sB[0][0]);
    const u32 BUF = 128 * 40 * 2;
    if (tid < 128) {
        int bt = bt0 + tid;
        int b = bt / T_, t = bt - b * T_;
        int tp = t + ksh - 1;
        rowBase[tid] = (tp >= 0 && tp < T_) ? ((b * T_ + tp) * KSH_) : -1;
    }
    __syncthreads();
    u32 aAddr[2];
    #pragma unroll
    for (int mi = 0; mi < 2; mi++) {
        int row = wm * 32 + mi * 16 + (grp & 1) * 8 + lr;
        aAddr[mi] = saB + (row * 40 + (grp >> 1) * 8) * 2;
    }
    const u32 bAddr = sbB + ((wn * 64 + (grp >> 1) * 8 + lr) * 40 + (grp & 1) * 8) * 2;
    const int r_ = tid >> 2, sub_ = tid & 3;
    const int base_ = rowBase[r_], base64_ = rowBase[r_ + 64];
    float c[2][8][4] = {};

    // prologue
    #pragma unroll
    for (int t = 0; t < 2; t++) {
        int r = r_ + t * 64, sub = sub_;
        u32 d = (r * 40 + (sub >> 1) * 16 + (sub & 1) * 8) * 2;
        int base = t ? base64_ : base_;
        const bf16* sa = (base >= 0)
            ? (sub < 2 ? g_Bh : g_Bl) + (size_t)base + koff + (sub & 1) * 8
            : g_zero + (sub & 1) * 8;
        cp16(saB + d, sa);
        cp16(sbB + d, (sub < 2 ? g_w1ph : g_w1pl) + (size_t)r * KCONV + kb0 + (sub & 1) * 8);
    }
    CP_COMMIT();

    for (int s = 0; s < CKCH / 16; s++) {
        const int bi = s & 1;
        CP_WAIT0();
        __syncthreads();
        const u32 bo = bi * BUF;
        u32 ah[2][4], al[2][4];
        #pragma unroll
        for (int mi = 0; mi < 2; mi++) {
            ldsm4(ah[mi][0], ah[mi][1], ah[mi][2], ah[mi][3], aAddr[mi] + bo);
            ldsm4(al[mi][0], al[mi][1], al[mi][2], al[mi][3], aAddr[mi] + bo + 32);
        }
        if (s < CKCH / 16 - 1) {
            const int kk0 = (s + 1) * 16;
            const u32 bo2 = (bi ^ 1) * BUF;
            #pragma unroll
            for (int t = 0; t < 2; t++) {
                int r = r_ + t * 64, sub = sub_;
                u32 d = bo2 + (r * 40 + (sub >> 1) * 16 + (sub & 1) * 8) * 2;
                int base = t ? base64_ : base_;
                const bf16* sa = (base >= 0)
                    ? (sub < 2 ? g_Bh : g_Bl) + (size_t)base + koff + kk0 + (sub & 1) * 8
                    : g_zero + (sub & 1) * 8;
                cp16(saB + d, sa);
                cp16(sbB + d, (sub < 2 ? g_w1ph : g_w1pl) + (size_t)r * KCONV + kb0 + kk0 + (sub & 1) * 8);
            }
            CP_COMMIT();
        }
        #pragma unroll
        for (int p = 0; p < 4; p++) {
            const u32 ba = bAddr + bo + p * 1280;
            u32 bh[4], bl[4];
            ldsm4(bh[0], bh[1], bh[2], bh[3], ba);
            ldsm4(bl[0], bl[1], bl[2], bl[3], ba + 32);
            #pragma unroll
            for (int mi = 0; mi < 2; mi++) {
                mma_bf16(c[mi][2 * p],     ah[mi], bh[0], bh[1]);
                mma_bf16(c[mi][2 * p],     ah[mi], bl[0], bl[1]);
                mma_bf16(c[mi][2 * p],     al[mi], bh[0], bh[1]);
                mma_bf16(c[mi][2 * p + 1], ah[mi], bh[2], bh[3]);
                mma_bf16(c[mi][2 * p + 1], ah[mi], bl[2], bl[3]);
                mma_bf16(c[mi][2 * p + 1], al[mi], bh[2], bh[3]);
            }
        }
    }
    #pragma unroll
    for (int mi = 0; mi < 2; mi++) {
        int btlo = bt0 + wm * 32 + mi * 16 + g;
        int bthi = btlo + 8;
        #pragma unroll
        for (int nj = 0; nj < 8; nj++) {
            int cc = wn * 64 + nj * 8 + tig * 2;
            *(float2*)&g_y1part[((size_t)ks * BT_ + btlo) * C_ + cc] =
                make_float2(c[mi][nj][0], c[mi][nj][1]);
            *(float2*)&g_y1part[((size_t)ks * BT_ + bthi) * C_ + cc] =
                make_float2(c[mi][nj][2], c[mi][nj][3]);
        }
    }
}

// ---------------- K-D: conv2 + relu + temporal mean-pool ----------------
__global__ void k_conv2pool(const float* __restrict__ cb1,
                            const float* __restrict__ w2,
                            const float* __restrict__ cb2)
{
    __shared__ float ys[C_ * 26];
    const int b = blockIdx.x;
    const int tid = threadIdx.x;
    for (int i = tid; i < C_ * T_; i += 256) {
        int c = i & 127, t = i >> 7;
        float v = cb1[c];
        #pragma unroll
        for (int s = 0; s < CSK; s++)
            v += g_y1part[((size_t)s * BT_ + b * T_ + t) * C_ + c];
        ys[c * 26 + t + 1] = fmaxf(v, 0.f);
    }
    if (tid < C_) { ys[tid * 26 + 0] = 0.f; ys[tid * 26 + 25] = 0.f; }
    __syncthreads();

    const int c = tid >> 1;
    const int half = tid & 1;
    const int tbase = half * 12;
    const float bias2 = cb2[c];
    const float* wrow = w2 + c * (C_ * 3);
    float acc[12];
    #pragma unroll
    for (int tt = 0; tt < 12; tt++) acc[tt] = bias2;
    for (int c1 = 0; c1 < C_; c1++) {
        float w0 = wrow[c1 * 3 + 0];
        float w1 = wrow[c1 * 3 + 1];
        float w2v = wrow[c1 * 3 + 2];
        float yv[14];
        #pragma unroll
        for (int idx = 0; idx < 14; idx++) yv[idx] = ys[c1 * 26 + tbase + idx];
        #pragma unroll
        for (int tt = 0; tt < 12; tt++)
            acc[tt] += w0 * yv[tt] + w1 * yv[tt + 1] + w2v * yv[tt + 2];
    }
    float s = 0.f;
    #pragma unroll
    for (int tt = 0; tt < 12; tt++) s += fmaxf(acc[tt], 0.f);
    s += __shfl_xor_sync(0xffffffffu, s, 1);
    if (half == 0) g_pooled[b * C_ + c] = s * (1.f / 24.f);
}

// ---------------- K-E: MLP1 split-K 16, fp32 scalar ----------------
__global__ void k_mlp1(const float* __restrict__ w)
{
    const int n0  = blockIdx.x * 64;
    const int kc0 = blockIdx.y * MLP1_KCH;
    __shared__ float Ast[16][68];
    __shared__ float Bs[16][68];
    const int tid = threadIdx.x;
    const int tx = tid & 15, ty = tid >> 4;
    float acc[4][4] = {};
    for (int k0 = 0; k0 < MLP1_KCH; k0 += 16) {
        for (int i = tid; i < 1024; i += 256) {
            int r = i >> 4, k = i & 15;
            int kg = kc0 + k0 + k;
            float v;
            if (kg < ND_) {
                int nn = kg >> 6, d = kg & 63;
                size_t a = ((size_t)((r * T_ + (T_ - 1)) * 64 + d)) * NP + nn;
                v = __bfloat162float(g_Bh[a]) + __bfloat162float(g_Bl[a]);
            } else if (kg < MLPIN_) {
                v = g_pooled[r * C_ + (kg - ND_)];
            } else {
                v = 0.f;
            }
            Ast[k][r] = v;
        }
        for (int i = tid; i < 1024; i += 256) {
            int k = i >> 6, d = i & 63;
            int kg = kc0 + k0 + k;
            Bs[k][d] = (kg < MLPIN_) ? w[(size_t)kg * 512 + n0 + d] : 0.f;
        }
        __syncthreads();
        #pragma unroll
        for (int k = 0; k < 16; k++) {
            float4 a4 = *reinterpret_cast<const float4*>(&Ast[k][ty * 4]);
            float4 b4 = *reinterpret_cast<const float4*>(&Bs[k][tx * 4]);
            float a[4] = {a4.x, a4.y, a4.z, a4.w};
            float b[4] = {b4.x, b4.y, b4.z, b4.w};
            #pragma unroll
            for (int i = 0; i < 4; i++)
                #pragma unroll
                for (int j = 0; j < 4; j++) acc[i][j] = fmaf(a[i], b[j], acc[i][j]);
        }
        __syncthreads();
    }
    const int ks = blockIdx.y;
    #pragma unroll
    for (int i = 0; i < 4; i++)
        #pragma unroll
        for (int j = 0; j < 4; j++)
            g_z1part[(ks * B_ + ty * 4 + i) * 512 + n0 + tx * 4 + j] = acc[i][j];
}

// ---------------- K-F: MLP2 ----------------
__global__ void k_mlp2(const float* __restrict__ mb1, const float* __restrict__ w,
                       const float* __restrict__ mb2)
{
    const int n0 = blockIdx.x * 64;
    __shared__ float Ast[16][68];
    __shared__ float Bs[16][68];
    const int tid = threadIdx.x;
    const int tx = tid & 15, ty = tid >> 4;
    float acc[4][4] = {};
    for (int k0 = 0; k0 < 512; k0 += 16) {
        for (int i = tid; i < 1024; i += 256) {
            int r = i >> 4, k = i & 15;
            int kg = k0 + k;
            float v = mb1[kg];
            #pragma unroll
            for (int s = 0; s < MLP1_SK; s++) v += g_z1part[(s * B_ + r) * 512 + kg];
            Ast[k][r] = fmaxf(v, 0.f);
        }
        for (int i = tid; i < 1024; i += 256) {
            int k = i >> 6, d = i & 63;
            Bs[k][d] = w[(k0 + k) * 256 + n0 + d];
        }
        __syncthreads();
        #pragma unroll
        for (int k = 0; k < 16; k++) {
            float4 a4 = *reinterpret_cast<const float4*>(&Ast[k][ty * 4]);
            float4 b4 = *reinterpret_cast<const float4*>(&Bs[k][tx * 4]);
            float a[4] = {a4.x, a4.y, a4.z, a4.w};
            float b[4] = {b4.x, b4.y, b4.z, b4.w};
            #pragma unroll
            for (int i = 0; i < 4; i++)
                #pragma unroll
                for (int j = 0; j < 4; j++) acc[i][j] = fmaf(a[i], b[j], acc[i][j]);
        }
        __syncthreads();
    }
    #pragma unroll
    for (int i = 0; i < 4; i++)
        #pragma unroll
        for (int j = 0; j < 4; j++) {
            int n = n0 + tx * 4 + j;
            g_z2[(ty * 4 + i) * 256 + n] = fmaxf(acc[i][j] + mb2[n], 0.f);
        }
}

// ---------------- K-G: MLP3 -> d_out ----------------
__global__ void k_mlp3(const float* __restrict__ w, const float* __restrict__ mb3,
                       float* __restrict__ out)
{
    const int n0 = blockIdx.x * 64;
    __shared__ float Ast[16][68];
    __shared__ float Bs[16][68];
    const int tid = threadIdx.x;
    const int tx = tid & 15, ty = tid >> 4;
    float acc[4][4] = {};
    for (int k0 = 0; k0 < 256; k0 += 16) {
        for (int i = tid; i < 1024; i += 256) {
            int r = i >> 4, k = i & 15;
            Ast[k][r] = g_z2[r * 256 + k0 + k];
        }
        for (int i = tid; i < 1024; i += 256) {
            int k = i >> 6, d = i & 63;
            int n = n0 + d;
            Bs[k][d] = (n < N_ * H_) ? w[(k0 + k) * (N_ * H_) + n] : 0.f;
        }
        __syncthreads();
        #pragma unroll
        for (int k = 0; k < 16; k++) {
            float4 a4 = *reinterpret_cast<const float4*>(&Ast[k][ty * 4]);
            float4 b4 = *reinterpret_cast<const float4*>(&Bs[k][tx * 4]);
            float a[4] = {a4.x, a4.y, a4.z, a4.w};
            float b[4] = {b4.x, b4.y, b4.z, b4.w};
            #pragma unroll
            for (int i = 0; i < 4; i++)
                #pragma unroll
                for (int j = 0; j < 4; j++) acc[i][j] = fmaf(a[i], b[j], acc[i][j]);
        }
        __syncthreads();
    }
    #pragma unroll
    for (int i = 0; i < 4; i++)
        #pragma unroll
        for (int j = 0; j < 4; j++) {
            int n = n0 + tx * 4 + j;
            if (n < N_ * H_)
                out[(ty * 4 + i) * (N_ * H_) + n] = acc[i][j] + mb3[n];
        }
}

// ---------------- launch ----------------
extern "C" void kernel_launch(void* const* d_in, const int* in_sizes, int n_in,
                              void* d_out, int out_size)
{
    const float* x    = (const float*)d_in[0];
    const float* adj  = (const float*)d_in[1];
    const float* gw1  = (const float*)d_in[2];
    const float* gb1  = (const float*)d_in[3];
    const float* gw2  = (const float*)d_in[4];
    const float* gb2  = (const float*)d_in[5];
    const float* cw1  = (const float*)d_in[6];
    const float* cb1  = (const float*)d_in[7];
    const float* cw2  = (const float*)d_in[8];
    const float* cb2  = (const float*)d_in[9];
    const float* mw1  = (const float*)d_in[10];
    const float* mb1  = (const float*)d_in[11];
    const float* mw2  = (const float*)d_in[12];
    const float* mb2  = (const float*)d_in[13];
    const float* mw3  = (const float*)d_in[14];
    const float* mb3  = (const float*)d_in[15];
    float* out = (float*)d_out;

    bf16 *Ah, *Al, *Bh, *Bl;
    cudaGetSymbolAddress((void**)&Ah, g_Ah);
    cudaGetSymbolAddress((void**)&Al, g_Al);
    cudaGetSymbolAddress((void**)&Bh, g_Bh);
    cudaGetSymbolAddress((void**)&Bl, g_Bl);

    cudaFuncSetAttribute(k_hw2, cudaFuncAttributeMaxDynamicSharedMemorySize, HW2_SMEM);

    k_prep<<<(300 * NP + 4096 + 255) / 256, 256>>>(adj, gw2);
    k_repack<<<dim3(C_, 6), 256>>>(cw1);
    k_xw1<<<BTN_ / 64, 256>>>(x, gw1);                                    // S1 -> A
    k_adjmm<128><<<dim3(Q_ / 128, 2), 256>>>(Ah, Al, gb1, Bh, Bl);
    k_adjmm<64><<<dim3(Q_ / 128, 1), 256>>>(Ah, Al, gb1, Bh, Bl);         // h1 -> B
    k_hw2<<<BT_, 256, HW2_SMEM>>>();                                      // S2 -> A
    k_adjmm<128><<<dim3(Q_ / 128, 2), 256>>>(Ah, Al, gb2, Bh, Bl);
    k_adjmm<64><<<dim3(Q_ / 128, 1), 256>>>(Ah, Al, gb2, Bh, Bl);         // h2 -> B
    k_conv1<<<dim3(BT_ / 128, CSK), 256>>>();
    k_conv2pool<<<B_, 256>>>(cb1, cw2, cb2);
    k_mlp1<<<dim3(512 / 64, MLP1_SK), 256>>>(mw1);
    k_mlp2<<<256 / 64, 256>>>(mb1, mw2, mb2);
    k_mlp3<<<(N_ * H_ + 63) / 64, 256>>>(mw3, mb3, out);
}